// round 3
// baseline (speedup 1.0000x reference)
#include <cuda_runtime.h>

#define EPS 1e-6f

// x: (2048, 4096, 16) fp32  -> 8,388,608 rows of 16 floats (64 B each)
// Grade slices over last dim: [0,1) [1,5) [5,11) [11,15) [15,16)
// out[..., a:b] = x[..., a:b] * rsqrt(sum(x[a:b]^2) + eps) * scale[g]

__global__ void __launch_bounds__(256)
gradewise_ln_kernel(const float4* __restrict__ x,
                    const float*  __restrict__ scale,
                    float4* __restrict__ out,
                    int nrows)
{
    int row = blockIdx.x * blockDim.x + threadIdx.x;
    if (row >= nrows) return;

    size_t base = (size_t)row * 4;  // 4 float4 per row

    float4 a = x[base + 0];
    float4 b = x[base + 1];
    float4 c = x[base + 2];
    float4 d = x[base + 3];

    // grade sums of squares
    float s0 = a.x * a.x;
    float s1 = a.y * a.y + a.z * a.z + a.w * a.w + b.x * b.x;
    float s2 = b.y * b.y + b.z * b.z + b.w * b.w
             + c.x * c.x + c.y * c.y + c.z * c.z;
    float s3 = c.w * c.w + d.x * d.x + d.y * d.y + d.z * d.z;
    float s4 = d.w * d.w;

    float r0 = rsqrtf(s0 + EPS) * __ldg(&scale[0]);
    float r1 = rsqrtf(s1 + EPS) * __ldg(&scale[1]);
    float r2 = rsqrtf(s2 + EPS) * __ldg(&scale[2]);
    float r3 = rsqrtf(s3 + EPS) * __ldg(&scale[3]);
    float r4 = rsqrtf(s4 + EPS) * __ldg(&scale[4]);

    float4 oa, ob, oc, od;
    oa.x = a.x * r0;
    oa.y = a.y * r1;  oa.z = a.z * r1;  oa.w = a.w * r1;
    ob.x = b.x * r1;
    ob.y = b.y * r2;  ob.z = b.z * r2;  ob.w = b.w * r2;
    oc.x = c.x * r2;  oc.y = c.y * r2;  oc.z = c.z * r2;
    oc.w = c.w * r3;
    od.x = d.x * r3;  od.y = d.y * r3;  od.z = d.z * r3;
    od.w = d.w * r4;

    out[base + 0] = oa;
    out[base + 1] = ob;
    out[base + 2] = oc;
    out[base + 3] = od;
}

extern "C" void kernel_launch(void* const* d_in, const int* in_sizes, int n_in,
                              void* d_out, int out_size)
{
    const float4* x     = (const float4*)d_in[0];
    const float*  scale = (const float*)d_in[1];
    float4*       out   = (float4*)d_out;

    int nrows = in_sizes[0] / 16;  // 2048*4096 = 8,388,608

    const int threads = 256;
    int blocks = (nrows + threads - 1) / threads;

    gradewise_ln_kernel<<<blocks, threads>>>(x, scale, out, nrows);
}